// round 6
// baseline (speedup 1.0000x reference)
#include <cuda_runtime.h>
#include <cuda_bf16.h>
#include <mma.h>
#include <math.h>
#include <stdint.h>

using namespace nvcuda;

#define BB   32
#define SS   200
#define SM1  199
#define MTOT (BB*SM1)   // 6368
#define MPAD 6400       // 50 * 128
#define MC   4

typedef unsigned long long ull;

// ---------------- device-global scratch ----------------
__device__ float d_emb_qc[(size_t)BB*SS*512];
__device__ float d_gx[(size_t)MTOT*1024];
__device__ float d_hall[(size_t)MTOT*256];
__device__ float d_hq[(size_t)MTOT*768];
__device__ float d_hc[(size_t)MTOT*768];
__device__ float d_hqa[(size_t)MTOT*256];
__device__ float d_hca[(size_t)MTOT*256];

// bf16 hi/lo split operands (pad rows stay zero)
__device__ __nv_bfloat16 g_qca_hi[(size_t)MPAD*1024];
__device__ __nv_bfloat16 g_qca_lo[(size_t)MPAD*1024];
__device__ __nv_bfloat16 g_wih_hi[1024*1024];
__device__ __nv_bfloat16 g_wih_lo[1024*1024];
__device__ __nv_bfloat16 g_hnx_hi[(size_t)MPAD*768];
__device__ __nv_bfloat16 g_hnx_lo[(size_t)MPAD*768];
__device__ __nv_bfloat16 g_hal_hi[(size_t)MPAD*256];
__device__ __nv_bfloat16 g_hal_lo[(size_t)MPAD*256];
__device__ __nv_bfloat16 g_wqn_hi[768*768];
__device__ __nv_bfloat16 g_wqn_lo[768*768];
__device__ __nv_bfloat16 g_wcn_hi[768*768];
__device__ __nv_bfloat16 g_wcn_lo[768*768];
__device__ __nv_bfloat16 g_wqa_hi[256*256];
__device__ __nv_bfloat16 g_wqa_lo[256*256];
__device__ __nv_bfloat16 g_wca_hi[256*256];
__device__ __nv_bfloat16 g_wca_lo[256*256];

__device__ __forceinline__ float sigmoidf_(float x) { return 1.f / (1.f + expf(-x)); }

// fast, clamped pointwise (err ~1e-7, safe for __fdividef range)
__device__ __forceinline__ float fast_sig(float x) {
    x = fmaxf(fminf(x, 30.f), -30.f);
    return __fdividef(1.f, 1.f + __expf(-x));
}
__device__ __forceinline__ float fast_tanh(float x) {
    x = fmaxf(fminf(x, 15.f), -15.f);
    float t = __expf(2.f * x);
    return __fdividef(t - 1.f, t + 1.f);
}

__device__ __forceinline__ void wsplit(__nv_bfloat16* hi, __nv_bfloat16* lo, size_t i, float v) {
    __nv_bfloat16 h = __float2bfloat16_rn(v);
    hi[i] = h;
    lo[i] = __float2bfloat16_rn(v - __bfloat162float(h));
}

// f32x2 helpers
__device__ __forceinline__ void fma2(ull &acc, ull a, ull b) {
    asm("fma.rn.f32x2 %0, %1, %2, %0;" : "+l"(acc) : "l"(a), "l"(b));
}
__device__ __forceinline__ float2 upk(ull v) {
    float2 r; asm("mov.b64 {%0,%1}, %2;" : "=f"(r.x), "=f"(r.y) : "l"(v)); return r;
}
__device__ __forceinline__ uint32_t smem_u32(const void* p) {
    uint32_t a;
    asm("{ .reg .u64 t; cvta.to.shared.u64 t, %1; cvt.u32.u64 %0, t; }" : "=r"(a) : "l"(p));
    return a;
}
__device__ __forceinline__ void st_dsmem(uint32_t addr, float v) {
    asm volatile("st.shared::cluster.f32 [%0], %1;" :: "r"(addr), "f"(v) : "memory");
}
__device__ __forceinline__ uint32_t mapa_(uint32_t addr, uint32_t rank) {
    uint32_t r;
    asm("mapa.shared::cluster.u32 %0, %1, %2;" : "=r"(r) : "r"(addr), "r"(rank));
    return r;
}
__device__ __forceinline__ void cluster_sync_() {
    asm volatile("barrier.cluster.arrive.aligned;" ::: "memory");
    asm volatile("barrier.cluster.wait.aligned;" ::: "memory");
}
__device__ __forceinline__ void mbar_init(uint32_t mbar, uint32_t cnt) {
    asm volatile("mbarrier.init.shared.b64 [%0], %1;" :: "r"(mbar), "r"(cnt) : "memory");
}
__device__ __forceinline__ void mbar_arrive_remote(uint32_t raddr) {
    asm volatile("mbarrier.arrive.release.cluster.shared::cluster.b64 _, [%0];"
                 :: "r"(raddr) : "memory");
}
__device__ __forceinline__ void mbar_wait_cl(uint32_t mbar, uint32_t parity) {
    asm volatile(
        "{\n\t.reg .pred P1;\n\t"
        "WAIT_LOOP_%=:\n\t"
        "mbarrier.try_wait.parity.acquire.cluster.shared::cta.b64 P1, [%0], %1, 0x989680;\n\t"
        "@P1 bra.uni WAIT_DONE_%=;\n\t"
        "bra.uni WAIT_LOOP_%=;\n\t"
        "WAIT_DONE_%=:\n\t}"
        :: "r"(mbar), "r"(parity) : "memory");
}

// ---------------- embeddings + LSTM-input assembly ----------------
__global__ void embed_kernel(const int* __restrict__ q, const int* __restrict__ c,
                             const int* __restrict__ r,
                             const float* __restrict__ que_emb,
                             const float* __restrict__ concept_emb) {
    int bs = blockIdx.x;
    int b = bs / SS, s = bs % SS;
    int e = threadIdx.x;
    int qi = q[bs];
    float eq = que_emb[(size_t)qi*256 + e];
    float sum = 0.f; int cnt = 0;
    #pragma unroll
    for (int j = 0; j < MC; j++) {
        int cj = c[bs*MC + j];
        if (cj >= 0) { sum += concept_emb[(size_t)cj*256 + e]; cnt++; }
    }
    float ec = sum / (float)max(cnt, 1);
    size_t base = (size_t)bs * 512;
    d_emb_qc[base + e]       = eq;
    d_emb_qc[base + 256 + e] = ec;
    if (s < SM1) {
        float f1 = (float)r[bs];
        float f0 = 1.f - f1;
        size_t mb = ((size_t)b*SM1 + s) * 1024;
        wsplit(g_qca_hi, g_qca_lo, mb + e,       eq * f0);
        wsplit(g_qca_hi, g_qca_lo, mb + 256 + e, ec * f0);
        wsplit(g_qca_hi, g_qca_lo, mb + 512 + e, eq * f1);
        wsplit(g_qca_hi, g_qca_lo, mb + 768 + e, ec * f1);
    }
}

// ---------------- hnext (bf16 split) ----------------
__global__ void hnext_kernel() {
    int m = blockIdx.x;
    int b = m / SM1, t = m % SM1;
    int e = threadIdx.x;
    size_t src = ((size_t)b*SS + (t+1)) * 512;
    wsplit(g_hnx_hi, g_hnx_lo, (size_t)m*768 + e,       d_emb_qc[src + e]);
    wsplit(g_hnx_hi, g_hnx_lo, (size_t)m*768 + 256 + e, d_emb_qc[src + 256 + e]);
    wsplit(g_hnx_hi, g_hnx_lo, (size_t)m*768 + 512 + e, d_hall[(size_t)m*256 + e]);
}

// ---------------- f32 -> bf16 hi/lo split converter ----------------
__global__ void cvt_split(const float* __restrict__ s, __nv_bfloat16* __restrict__ hi,
                          __nv_bfloat16* __restrict__ lo, int n) {
    int i = (blockIdx.x * 256 + threadIdx.x) * 4;
    if (i >= n) return;
    float4 v = *reinterpret_cast<const float4*>(s + i);
    __nv_bfloat16 h0 = __float2bfloat16_rn(v.x), h1 = __float2bfloat16_rn(v.y);
    __nv_bfloat16 h2 = __float2bfloat16_rn(v.z), h3 = __float2bfloat16_rn(v.w);
    __nv_bfloat16 l0 = __float2bfloat16_rn(v.x - __bfloat162float(h0));
    __nv_bfloat16 l1 = __float2bfloat16_rn(v.y - __bfloat162float(h1));
    __nv_bfloat16 l2 = __float2bfloat16_rn(v.z - __bfloat162float(h2));
    __nv_bfloat16 l3 = __float2bfloat16_rn(v.w - __bfloat162float(h3));
    reinterpret_cast<__nv_bfloat162*>(hi + i)[0] = __halves2bfloat162(h0, h1);
    reinterpret_cast<__nv_bfloat162*>(hi + i)[1] = __halves2bfloat162(h2, h3);
    reinterpret_cast<__nv_bfloat162*>(lo + i)[0] = __halves2bfloat162(l0, l1);
    reinterpret_cast<__nv_bfloat162*>(lo + i)[1] = __halves2bfloat162(l2, l3);
}

// ---------------- wmma bf16-split GEMM (unchanged from R5) ----------------
#define GEMM_SMEM 40960
__global__ __launch_bounds__(256) void mma_gemm(
    const __nv_bfloat16* __restrict__ Ahi, const __nv_bfloat16* __restrict__ Alo,
    const __nv_bfloat16* __restrict__ Bhi, const __nv_bfloat16* __restrict__ Blo,
    const float* __restrict__ bias, const float* __restrict__ bias2,
    float* __restrict__ C, int M, int N, int K, int relu)
{
    extern __shared__ __align__(16) char smem[];
    __shared__ float sbias[128];
    __nv_bfloat16* tile[4];
    tile[0] = reinterpret_cast<__nv_bfloat16*>(smem);
    tile[1] = tile[0] + 5120;
    tile[2] = tile[1] + 5120;
    tile[3] = tile[2] + 5120;

    int tid = threadIdx.x;
    int w = tid >> 5, lane = tid & 31;
    int wm = w >> 1, wn = w & 1;
    int m0 = blockIdx.y * 128, n0 = blockIdx.x * 128;

    if (tid < 128) sbias[tid] = bias[n0 + tid] + (bias2 ? bias2[n0 + tid] : 0.f);

    wmma::fragment<wmma::accumulator, 16, 16, 16, float> acc[2][4];
    #pragma unroll
    for (int i = 0; i < 2; i++)
        #pragma unroll
        for (int j = 0; j < 4; j++) wmma::fill_fragment(acc[i][j], 0.f);

    const __nv_bfloat16* mats[4] = {Ahi, Alo, Bhi, Blo};
    const int r0s[4] = {m0, m0, n0, n0};

    for (int k0 = 0; k0 < K; k0 += 32) {
        #pragma unroll
        for (int mt = 0; mt < 4; mt++) {
            #pragma unroll
            for (int i = 0; i < 2; i++) {
                int o = i * 256 + tid;
                int row = o >> 2, c8 = (o & 3) * 8;
                *reinterpret_cast<float4*>(tile[mt] + row * 40 + c8) =
                    *reinterpret_cast<const float4*>(mats[mt] + (size_t)(r0s[mt] + row) * K + k0 + c8);
            }
        }
        __syncthreads();

        #pragma unroll
        for (int ks = 0; ks < 32; ks += 16) {
            wmma::fragment<wmma::matrix_a, 16, 16, 16, __nv_bfloat16, wmma::row_major> ah[2], al[2];
            #pragma unroll
            for (int i = 0; i < 2; i++) {
                wmma::load_matrix_sync(ah[i], tile[0] + (wm*32 + i*16) * 40 + ks, 40);
                wmma::load_matrix_sync(al[i], tile[1] + (wm*32 + i*16) * 40 + ks, 40);
            }
            #pragma unroll
            for (int j = 0; j < 4; j++) {
                wmma::fragment<wmma::matrix_b, 16, 16, 16, __nv_bfloat16, wmma::col_major> bh, bl;
                wmma::load_matrix_sync(bh, tile[2] + (wn*64 + j*16) * 40 + ks, 40);
                wmma::load_matrix_sync(bl, tile[3] + (wn*64 + j*16) * 40 + ks, 40);
                #pragma unroll
                for (int i = 0; i < 2; i++) {
                    wmma::mma_sync(acc[i][j], ah[i], bh, acc[i][j]);
                    wmma::mma_sync(acc[i][j], ah[i], bl, acc[i][j]);
                    wmma::mma_sync(acc[i][j], al[i], bh, acc[i][j]);
                }
            }
        }
        __syncthreads();
    }

    float* stage = reinterpret_cast<float*>(smem) + w * 320;
    int r = lane >> 1, c0 = (lane & 1) * 8;
    #pragma unroll
    for (int i = 0; i < 2; i++) {
        #pragma unroll
        for (int j = 0; j < 4; j++) {
            wmma::store_matrix_sync(stage, acc[i][j], 20, wmma::mem_row_major);
            __syncwarp();
            int gm = m0 + wm*32 + i*16 + r;
            if (gm < M) {
                int nc = wn*64 + j*16 + c0;
                float4 v0, v1;
                v0.x = stage[r*20 + c0 + 0] + sbias[nc + 0];
                v0.y = stage[r*20 + c0 + 1] + sbias[nc + 1];
                v0.z = stage[r*20 + c0 + 2] + sbias[nc + 2];
                v0.w = stage[r*20 + c0 + 3] + sbias[nc + 3];
                v1.x = stage[r*20 + c0 + 4] + sbias[nc + 4];
                v1.y = stage[r*20 + c0 + 5] + sbias[nc + 5];
                v1.z = stage[r*20 + c0 + 6] + sbias[nc + 6];
                v1.w = stage[r*20 + c0 + 7] + sbias[nc + 7];
                if (relu) {
                    v0.x = fmaxf(v0.x, 0.f); v0.y = fmaxf(v0.y, 0.f);
                    v0.z = fmaxf(v0.z, 0.f); v0.w = fmaxf(v0.w, 0.f);
                    v1.x = fmaxf(v1.x, 0.f); v1.y = fmaxf(v1.y, 0.f);
                    v1.z = fmaxf(v1.z, 0.f); v1.w = fmaxf(v1.w, 0.f);
                }
                *reinterpret_cast<float4*>(&C[(size_t)gm * N + n0 + nc])     = v0;
                *reinterpret_cast<float4*>(&C[(size_t)gm * N + n0 + nc + 4]) = v1;
            }
            __syncwarp();
        }
    }
}

// ---------------- cluster LSTM v2: gate-major, register cell state, mbarrier sync ----
// 16 clusters x 8 CTAs, 2 batches/cluster. Thread (j,kg): j=tid>>3 (0..31),
// kg=tid&7 (k-slice of 32). Computes all 4 gates for (gj = rk*32+j, both batches).
__global__ __cluster_dims__(8,1,1) __launch_bounds__(256, 1)
void lstm_kernel(const float* __restrict__ w_hh) {
    __shared__ __align__(16) float hbuf[2][2][288];   // [phase][batch][kg*36 + idx]
    __shared__ __align__(8) unsigned long long mbar;

    int tid  = threadIdx.x;
    int lane = tid & 31;
    int rk   = blockIdx.x & 7;
    int cl   = blockIdx.x >> 3;
    int j    = tid >> 3;
    int kg   = tid & 7;
    int gj   = rk * 32 + j;

    // weights in registers: w2[gate][16] f32x2 over k-slice [kg*32, kg*32+32)
    ull w2[4][16];
    #pragma unroll
    for (int g = 0; g < 4; g++) {
        const ulonglong2* wp = reinterpret_cast<const ulonglong2*>(
            &w_hh[(size_t)(g*256 + gj) * 256 + kg*32]);
        #pragma unroll
        for (int i = 0; i < 8; i++) {
            ulonglong2 u = wp[i];
            w2[g][2*i]   = u.x;
            w2[g][2*i+1] = u.y;
        }
    }

    for (int i = tid; i < 2*2*288; i += 256) (&hbuf[0][0][0])[i] = 0.f;
    uint32_t mb = smem_u32(&mbar);
    if (tid == 0) mbar_init(mb, 64);   // 8 warps x 8 CTAs per phase
    __syncthreads();
    cluster_sync_();                   // mbar + zeroed hbuf visible cluster-wide

    uint32_t hb = smem_u32(&hbuf[0][0][0]);
    uint32_t rhb[8], rmb[8];
    #pragma unroll
    for (int rr = 0; rr < 8; rr++) {
        rhb[rr] = mapa_(hb, (uint32_t)rr);
        rmb[rr] = mapa_(mb, (uint32_t)rr);
    }

    const bool pw = (kg == 0);
    size_t gxb0 = ((size_t)(2*cl + 0) * SM1) * 1024 + gj;
    size_t gxb1 = ((size_t)(2*cl + 1) * SM1) * 1024 + gj;
    float gxc[8], gxn[8];
    if (pw) {
        #pragma unroll
        for (int g = 0; g < 4; g++) {
            gxc[g]     = __ldcg(&d_gx[gxb0 + g*256]);
            gxc[4 + g] = __ldcg(&d_gx[gxb1 + g*256]);
        }
    }
    float c0 = 0.f, c1 = 0.f;

    for (int t = 0; t < SM1; t++) {
        if (pw && t + 1 < SM1) {
            size_t o = (size_t)(t + 1) * 1024;
            #pragma unroll
            for (int g = 0; g < 4; g++) {
                gxn[g]     = __ldcg(&d_gx[gxb0 + o + g*256]);
                gxn[4 + g] = __ldcg(&d_gx[gxb1 + o + g*256]);
            }
        }
        int ph = t & 1;
        const ulonglong2* hp0 = reinterpret_cast<const ulonglong2*>(&hbuf[ph][0][kg*36]);
        const ulonglong2* hp1 = reinterpret_cast<const ulonglong2*>(&hbuf[ph][1][kg*36]);

        ull acc[4][2];
        #pragma unroll
        for (int g = 0; g < 4; g++) { acc[g][0] = 0ULL; acc[g][1] = 0ULL; }

        #pragma unroll
        for (int i = 0; i < 8; i++) {
            ulonglong2 u0 = hp0[i];
            ulonglong2 u1 = hp1[i];
            #pragma unroll
            for (int g = 0; g < 4; g++) {
                fma2(acc[g][0], w2[g][2*i],   u0.x);
                fma2(acc[g][0], w2[g][2*i+1], u0.y);
                fma2(acc[g][1], w2[g][2*i],   u1.x);
                fma2(acc[g][1], w2[g][2*i+1], u1.y);
            }
        }

        float s[8];
        #pragma unroll
        for (int g = 0; g < 4; g++) {
            float2 a0 = upk(acc[g][0]); s[g]     = a0.x + a0.y;
            float2 a1 = upk(acc[g][1]); s[4 + g] = a1.x + a1.y;
        }
        #pragma unroll
        for (int d = 4; d; d >>= 1) {
            #pragma unroll
            for (int v = 0; v < 8; v++)
                s[v] += __shfl_down_sync(0xffffffffu, s[v], d, 8);
        }

        if (pw) {
            float cn0 = fast_sig(s[1] + gxc[1]) * c0
                      + fast_sig(s[0] + gxc[0]) * fast_tanh(s[2] + gxc[2]);
            float h0  = fast_sig(s[3] + gxc[3]) * fast_tanh(cn0);
            float cn1 = fast_sig(s[5] + gxc[5]) * c1
                      + fast_sig(s[4] + gxc[4]) * fast_tanh(s[6] + gxc[6]);
            float h1  = fast_sig(s[7] + gxc[7]) * fast_tanh(cn1);
            c0 = cn0; c1 = cn1;

            size_t r0 = ((size_t)(2*cl + 0) * SM1 + t) * 256 + gj;
            size_t r1 = ((size_t)(2*cl + 1) * SM1 + t) * 256 + gj;
            d_hall[r0] = h0;
            d_hall[r1] = h1;
            __nv_bfloat16 hh0 = __float2bfloat16_rn(h0);
            __nv_bfloat16 hh1 = __float2bfloat16_rn(h1);
            g_hal_hi[r0] = hh0;
            g_hal_lo[r0] = __float2bfloat16_rn(h0 - __bfloat162float(hh0));
            g_hal_hi[r1] = hh1;
            g_hal_lo[r1] = __float2bfloat16_rn(h1 - __bfloat162float(hh1));

            uint32_t off0 = (uint32_t)((((t+1)&1)*2 + 0)*288 + rk*36 + j) * 4u;
            uint32_t off1 = off0 + 288u*4u;
            #pragma unroll
            for (int rr = 0; rr < 8; rr++) {
                st_dsmem(rhb[rr] + off0, h0);
                st_dsmem(rhb[rr] + off1, h1);
            }
            #pragma unroll
            for (int v = 0; v < 8; v++) gxc[v] = gxn[v];
        }
        __syncwarp();
        if (lane == 0) {
            #pragma unroll
            for (int rr = 0; rr < 8; rr++) mbar_arrive_remote(rmb[rr]);
        }
        mbar_wait_cl(mb, (uint32_t)(t & 1));
    }
    cluster_sync_();
}

// ---------------- gathered output heads ----------------
__device__ __forceinline__ float warp_sum(float v) {
    #pragma unroll
    for (int o = 16; o; o >>= 1) v += __shfl_xor_sync(0xffffffffu, v, o);
    return v;
}

__global__ __launch_bounds__(256) void gather_kernel(
    const int* __restrict__ qshft, const int* __restrict__ cshft,
    const float* __restrict__ qn_ow, const float* __restrict__ qn_ob,
    const float* __restrict__ cn_ow, const float* __restrict__ cn_ob,
    const float* __restrict__ qa_ow, const float* __restrict__ qa_ob,
    const float* __restrict__ ca_ow, const float* __restrict__ ca_ob,
    float* __restrict__ out)
{
    int m = blockIdx.x * 8 + (threadIdx.x >> 5);
    int lane = threadIdx.x & 31;

    float acc = 0.f;
    for (int k = lane; k < 768; k += 32)
        acc += d_hq[(size_t)m*768 + k] * qn_ow[k];
    float yqn = sigmoidf_(warp_sum(acc) + qn_ob[0]);

    float ysum = 0.f; int cnt = 0;
    #pragma unroll
    for (int j = 0; j < MC; j++) {
        int cc = cshft[m*MC + j];
        if (cc >= 0) {
            float a = 0.f;
            for (int k = lane; k < 768; k += 32)
                a += d_hc[(size_t)m*768 + k] * cn_ow[(size_t)cc*768 + k];
            ysum += sigmoidf_(warp_sum(a) + cn_ob[cc]);
            cnt++;
        }
    }
    float ycn = ysum / (float)max(cnt, 1);

    int qi = qshft[m];
    float a2 = 0.f;
    for (int k = lane; k < 256; k += 32)
        a2 += d_hqa[(size_t)m*256 + k] * qa_ow[(size_t)qi*256 + k];
    float yqa = sigmoidf_(warp_sum(a2) + qa_ob[qi]);

    float ysum2 = 0.f; int cnt2 = 0;
    #pragma unroll
    for (int j = 0; j < MC; j++) {
        int cc = cshft[m*MC + j];
        if (cc >= 0) {
            float a = 0.f;
            for (int k = lane; k < 256; k += 32)
                a += d_hca[(size_t)m*256 + k] * ca_ow[(size_t)cc*256 + k];
            ysum2 += sigmoidf_(warp_sum(a) + ca_ob[cc]);
            cnt2++;
        }
    }
    float yca = ysum2 / (float)max(cnt2, 1);

    if (lane == 0) {
        out[m]            = yqn;
        out[MTOT + m]     = ycn;
        out[2*MTOT + m]   = yqa;
        out[3*MTOT + m]   = yca;
    }
}

// ---------------- launch ----------------
extern "C" void kernel_launch(void* const* d_in, const int* in_sizes, int n_in,
                              void* d_out, int out_size) {
    const int*   q           = (const int*)d_in[0];
    const int*   c           = (const int*)d_in[1];
    const int*   r           = (const int*)d_in[2];
    const int*   qshft       = (const int*)d_in[3];
    const int*   cshft       = (const int*)d_in[4];
    const float* que_emb     = (const float*)d_in[5];
    const float* concept_emb = (const float*)d_in[6];
    const float* w_ih        = (const float*)d_in[7];
    const float* w_hh        = (const float*)d_in[8];
    const float* b_ih        = (const float*)d_in[9];
    const float* b_hh        = (const float*)d_in[10];
    const float* qn_lw = (const float*)d_in[11];
    const float* qn_lb = (const float*)d_in[12];
    const float* qn_ow = (const float*)d_in[13];
    const float* qn_ob = (const float*)d_in[14];
    const float* cn_lw = (const float*)d_in[15];
    const float* cn_lb = (const float*)d_in[16];
    const float* cn_ow = (const float*)d_in[17];
    const float* cn_ob = (const float*)d_in[18];
    const float* qa_lw = (const float*)d_in[19];
    const float* qa_lb = (const float*)d_in[20];
    const float* qa_ow = (const float*)d_in[21];
    const float* qa_ob = (const float*)d_in[22];
    const float* ca_lw = (const float*)d_in[23];
    const float* ca_lb = (const float*)d_in[24];
    const float* ca_ow = (const float*)d_in[25];
    const float* ca_ob = (const float*)d_in[26];
    float* out = (float*)d_out;

    float* p_gx;  cudaGetSymbolAddress((void**)&p_gx,  d_gx);
    float* p_hq;  cudaGetSymbolAddress((void**)&p_hq,  d_hq);
    float* p_hc;  cudaGetSymbolAddress((void**)&p_hc,  d_hc);
    float* p_hqa; cudaGetSymbolAddress((void**)&p_hqa, d_hqa);
    float* p_hca; cudaGetSymbolAddress((void**)&p_hca, d_hca);
    __nv_bfloat16 *p_qca_hi, *p_qca_lo, *p_wih_hi, *p_wih_lo;
    __nv_bfloat16 *p_hnx_hi, *p_hnx_lo, *p_hal_hi, *p_hal_lo;
    __nv_bfloat16 *p_wqn_hi, *p_wqn_lo, *p_wcn_hi, *p_wcn_lo;
    __nv_bfloat16 *p_wqa_hi, *p_wqa_lo, *p_wca_hi, *p_wca_lo;
    cudaGetSymbolAddress((void**)&p_qca_hi, g_qca_hi);
    cudaGetSymbolAddress((void**)&p_qca_lo, g_qca_lo);
    cudaGetSymbolAddress((void**)&p_wih_hi, g_wih_hi);
    cudaGetSymbolAddress((void**)&p_wih_lo, g_wih_lo);
    cudaGetSymbolAddress((void**)&p_hnx_hi, g_hnx_hi);
    cudaGetSymbolAddress((void**)&p_hnx_lo, g_hnx_lo);
    cudaGetSymbolAddress((void**)&p_hal_hi, g_hal_hi);
    cudaGetSymbolAddress((void**)&p_hal_lo, g_hal_lo);
    cudaGetSymbolAddress((void**)&p_wqn_hi, g_wqn_hi);
    cudaGetSymbolAddress((void**)&p_wqn_lo, g_wqn_lo);
    cudaGetSymbolAddress((void**)&p_wcn_hi, g_wcn_hi);
    cudaGetSymbolAddress((void**)&p_wcn_lo, g_wcn_lo);
    cudaGetSymbolAddress((void**)&p_wqa_hi, g_wqa_hi);
    cudaGetSymbolAddress((void**)&p_wqa_lo, g_wqa_lo);
    cudaGetSymbolAddress((void**)&p_wca_hi, g_wca_hi);
    cudaGetSymbolAddress((void**)&p_wca_lo, g_wca_lo);

    // (1) embeddings
    embed_kernel<<<BB*SS, 256>>>(q, c, r, que_emb, concept_emb);
    // (2) w_ih split
    cvt_split<<<(1024*1024/4 + 255)/256, 256>>>(w_ih, p_wih_hi, p_wih_lo, 1024*1024);
    // (3) gx = qca @ w_ih^T + b_ih + b_hh
    { dim3 g(8, 50); mma_gemm<<<g, 256, GEMM_SMEM>>>(p_qca_hi, p_qca_lo, p_wih_hi, p_wih_lo,
                                                     b_ih, b_hh, p_gx, MTOT, 1024, 1024, 0); }
    // (4) LSTM  <-- profiled launch slot
    lstm_kernel<<<128, 256>>>(w_hh);
    // (5) hnext assembly
    hnext_kernel<<<MTOT, 256>>>();
    // (6-9) weight splits
    cvt_split<<<(768*768/4 + 255)/256, 256>>>(qn_lw, p_wqn_hi, p_wqn_lo, 768*768);
    cvt_split<<<(768*768/4 + 255)/256, 256>>>(cn_lw, p_wcn_hi, p_wcn_lo, 768*768);
    cvt_split<<<(256*256/4 + 255)/256, 256>>>(qa_lw, p_wqa_hi, p_wqa_lo, 256*256);
    cvt_split<<<(256*256/4 + 255)/256, 256>>>(ca_lw, p_wca_hi, p_wca_lo, 256*256);
    // (10-13) hidden GEMMs
    { dim3 g(6, 50); mma_gemm<<<g, 256, GEMM_SMEM>>>(p_hnx_hi, p_hnx_lo, p_wqn_hi, p_wqn_lo,
                                                     qn_lb, nullptr, p_hq, MTOT, 768, 768, 1); }
    { dim3 g(6, 50); mma_gemm<<<g, 256, GEMM_SMEM>>>(p_hnx_hi, p_hnx_lo, p_wcn_hi, p_wcn_lo,
                                                     cn_lb, nullptr, p_hc, MTOT, 768, 768, 1); }
    { dim3 g(2, 50); mma_gemm<<<g, 256, GEMM_SMEM>>>(p_hal_hi, p_hal_lo, p_wqa_hi, p_wqa_lo,
                                                     qa_lb, nullptr, p_hqa, MTOT, 256, 256, 1); }
    { dim3 g(2, 50); mma_gemm<<<g, 256, GEMM_SMEM>>>(p_hal_hi, p_hal_lo, p_wca_hi, p_wca_lo,
                                                     ca_lb, nullptr, p_hca, MTOT, 256, 256, 1); }
    // (14) gathered heads
    gather_kernel<<<MTOT/8, 256>>>(qshft, cshft, qn_ow, qn_ob, cn_ow, cn_ob,
                                   qa_ow, qa_ob, ca_ow, ca_ob, out);
    (void)in_sizes; (void)n_in; (void)out_size;
}

// round 7
// speedup vs baseline: 1.5702x; 1.5702x over previous
#include <cuda_runtime.h>
#include <cuda_bf16.h>
#include <mma.h>
#include <math.h>
#include <stdint.h>

using namespace nvcuda;

#define BB   32
#define SS   200
#define SM1  199
#define MTOT (BB*SM1)   // 6368
#define MPAD 6400       // 50 * 128
#define MC   4

typedef unsigned long long ull;

// ---------------- device-global scratch ----------------
__device__ float d_emb_qc[(size_t)BB*SS*512];
__device__ float d_gx[(size_t)MTOT*1024];
__device__ float d_hall[(size_t)MTOT*256];
__device__ float d_hq[(size_t)MTOT*768];
__device__ float d_hc[(size_t)MTOT*768];
__device__ float d_hqa[(size_t)MTOT*256];
__device__ float d_hca[(size_t)MTOT*256];

// bf16 hi/lo split operands (pad rows stay zero)
__device__ __nv_bfloat16 g_qca_hi[(size_t)MPAD*1024];
__device__ __nv_bfloat16 g_qca_lo[(size_t)MPAD*1024];
__device__ __nv_bfloat16 g_wih_hi[1024*1024];
__device__ __nv_bfloat16 g_wih_lo[1024*1024];
__device__ __nv_bfloat16 g_hnx_hi[(size_t)MPAD*768];
__device__ __nv_bfloat16 g_hnx_lo[(size_t)MPAD*768];
__device__ __nv_bfloat16 g_hal_hi[(size_t)MPAD*256];
__device__ __nv_bfloat16 g_hal_lo[(size_t)MPAD*256];
__device__ __nv_bfloat16 g_wqn_hi[768*768];
__device__ __nv_bfloat16 g_wqn_lo[768*768];
__device__ __nv_bfloat16 g_wcn_hi[768*768];
__device__ __nv_bfloat16 g_wcn_lo[768*768];
__device__ __nv_bfloat16 g_wqa_hi[256*256];
__device__ __nv_bfloat16 g_wqa_lo[256*256];
__device__ __nv_bfloat16 g_wca_hi[256*256];
__device__ __nv_bfloat16 g_wca_lo[256*256];

__device__ __forceinline__ float sigmoidf_(float x) { return 1.f / (1.f + expf(-x)); }

// fast, clamped pointwise (err ~1e-7)
__device__ __forceinline__ float fast_sig(float x) {
    x = fmaxf(fminf(x, 30.f), -30.f);
    return __fdividef(1.f, 1.f + __expf(-x));
}
__device__ __forceinline__ float fast_tanh(float x) {
    x = fmaxf(fminf(x, 15.f), -15.f);
    float t = __expf(2.f * x);
    return __fdividef(t - 1.f, t + 1.f);
}

__device__ __forceinline__ void wsplit(__nv_bfloat16* hi, __nv_bfloat16* lo, size_t i, float v) {
    __nv_bfloat16 h = __float2bfloat16_rn(v);
    hi[i] = h;
    lo[i] = __float2bfloat16_rn(v - __bfloat162float(h));
}

// f32x2 helpers
__device__ __forceinline__ void fma2(ull &acc, ull a, ull b) {
    asm("fma.rn.f32x2 %0, %1, %2, %0;" : "+l"(acc) : "l"(a), "l"(b));
}
__device__ __forceinline__ float2 upk(ull v) {
    float2 r; asm("mov.b64 {%0,%1}, %2;" : "=f"(r.x), "=f"(r.y) : "l"(v)); return r;
}
__device__ __forceinline__ uint32_t smem_u32(const void* p) {
    uint32_t a;
    asm("{ .reg .u64 t; cvta.to.shared.u64 t, %1; cvt.u32.u64 %0, t; }" : "=r"(a) : "l"(p));
    return a;
}
__device__ __forceinline__ void st_dsmem(uint32_t addr, float v) {
    asm volatile("st.shared::cluster.f32 [%0], %1;" :: "r"(addr), "f"(v) : "memory");
}
__device__ __forceinline__ uint32_t mapa_(uint32_t addr, uint32_t rank) {
    uint32_t r;
    asm("mapa.shared::cluster.u32 %0, %1, %2;" : "=r"(r) : "r"(addr), "r"(rank));
    return r;
}
__device__ __forceinline__ void cluster_sync_() {
    asm volatile("barrier.cluster.arrive.aligned;" ::: "memory");
    asm volatile("barrier.cluster.wait.aligned;" ::: "memory");
}

// ---------------- embeddings + LSTM-input assembly ----------------
__global__ void embed_kernel(const int* __restrict__ q, const int* __restrict__ c,
                             const int* __restrict__ r,
                             const float* __restrict__ que_emb,
                             const float* __restrict__ concept_emb) {
    int bs = blockIdx.x;
    int b = bs / SS, s = bs % SS;
    int e = threadIdx.x;
    int qi = q[bs];
    float eq = que_emb[(size_t)qi*256 + e];
    float sum = 0.f; int cnt = 0;
    #pragma unroll
    for (int j = 0; j < MC; j++) {
        int cj = c[bs*MC + j];
        if (cj >= 0) { sum += concept_emb[(size_t)cj*256 + e]; cnt++; }
    }
    float ec = sum / (float)max(cnt, 1);
    size_t base = (size_t)bs * 512;
    d_emb_qc[base + e]       = eq;
    d_emb_qc[base + 256 + e] = ec;
    if (s < SM1) {
        float f1 = (float)r[bs];
        float f0 = 1.f - f1;
        size_t mb = ((size_t)b*SM1 + s) * 1024;
        wsplit(g_qca_hi, g_qca_lo, mb + e,       eq * f0);
        wsplit(g_qca_hi, g_qca_lo, mb + 256 + e, ec * f0);
        wsplit(g_qca_hi, g_qca_lo, mb + 512 + e, eq * f1);
        wsplit(g_qca_hi, g_qca_lo, mb + 768 + e, ec * f1);
    }
}

// ---------------- hnext (bf16 split) ----------------
__global__ void hnext_kernel() {
    int m = blockIdx.x;
    int b = m / SM1, t = m % SM1;
    int e = threadIdx.x;
    size_t src = ((size_t)b*SS + (t+1)) * 512;
    wsplit(g_hnx_hi, g_hnx_lo, (size_t)m*768 + e,       d_emb_qc[src + e]);
    wsplit(g_hnx_hi, g_hnx_lo, (size_t)m*768 + 256 + e, d_emb_qc[src + 256 + e]);
    wsplit(g_hnx_hi, g_hnx_lo, (size_t)m*768 + 512 + e, d_hall[(size_t)m*256 + e]);
}

// ---------------- f32 -> bf16 hi/lo split converter ----------------
__global__ void cvt_split(const float* __restrict__ s, __nv_bfloat16* __restrict__ hi,
                          __nv_bfloat16* __restrict__ lo, int n) {
    int i = (blockIdx.x * 256 + threadIdx.x) * 4;
    if (i >= n) return;
    float4 v = *reinterpret_cast<const float4*>(s + i);
    __nv_bfloat16 h0 = __float2bfloat16_rn(v.x), h1 = __float2bfloat16_rn(v.y);
    __nv_bfloat16 h2 = __float2bfloat16_rn(v.z), h3 = __float2bfloat16_rn(v.w);
    __nv_bfloat16 l0 = __float2bfloat16_rn(v.x - __bfloat162float(h0));
    __nv_bfloat16 l1 = __float2bfloat16_rn(v.y - __bfloat162float(h1));
    __nv_bfloat16 l2 = __float2bfloat16_rn(v.z - __bfloat162float(h2));
    __nv_bfloat16 l3 = __float2bfloat16_rn(v.w - __bfloat162float(h3));
    reinterpret_cast<__nv_bfloat162*>(hi + i)[0] = __halves2bfloat162(h0, h1);
    reinterpret_cast<__nv_bfloat162*>(hi + i)[1] = __halves2bfloat162(h2, h3);
    reinterpret_cast<__nv_bfloat162*>(lo + i)[0] = __halves2bfloat162(l0, l1);
    reinterpret_cast<__nv_bfloat162*>(lo + i)[1] = __halves2bfloat162(l2, l3);
}

// ---------------- wmma bf16-split GEMM ----------------
#define GEMM_SMEM 40960
__global__ __launch_bounds__(256) void mma_gemm(
    const __nv_bfloat16* __restrict__ Ahi, const __nv_bfloat16* __restrict__ Alo,
    const __nv_bfloat16* __restrict__ Bhi, const __nv_bfloat16* __restrict__ Blo,
    const float* __restrict__ bias, const float* __restrict__ bias2,
    float* __restrict__ C, int M, int N, int K, int relu)
{
    extern __shared__ __align__(16) char smem[];
    __shared__ float sbias[128];
    __nv_bfloat16* tile[4];
    tile[0] = reinterpret_cast<__nv_bfloat16*>(smem);
    tile[1] = tile[0] + 5120;
    tile[2] = tile[1] + 5120;
    tile[3] = tile[2] + 5120;

    int tid = threadIdx.x;
    int w = tid >> 5, lane = tid & 31;
    int wm = w >> 1, wn = w & 1;
    int m0 = blockIdx.y * 128, n0 = blockIdx.x * 128;

    if (tid < 128) sbias[tid] = bias[n0 + tid] + (bias2 ? bias2[n0 + tid] : 0.f);

    wmma::fragment<wmma::accumulator, 16, 16, 16, float> acc[2][4];
    #pragma unroll
    for (int i = 0; i < 2; i++)
        #pragma unroll
        for (int j = 0; j < 4; j++) wmma::fill_fragment(acc[i][j], 0.f);

    const __nv_bfloat16* mats[4] = {Ahi, Alo, Bhi, Blo};
    const int r0s[4] = {m0, m0, n0, n0};

    for (int k0 = 0; k0 < K; k0 += 32) {
        #pragma unroll
        for (int mt = 0; mt < 4; mt++) {
            #pragma unroll
            for (int i = 0; i < 2; i++) {
                int o = i * 256 + tid;
                int row = o >> 2, c8 = (o & 3) * 8;
                *reinterpret_cast<float4*>(tile[mt] + row * 40 + c8) =
                    *reinterpret_cast<const float4*>(mats[mt] + (size_t)(r0s[mt] + row) * K + k0 + c8);
            }
        }
        __syncthreads();

        #pragma unroll
        for (int ks = 0; ks < 32; ks += 16) {
            wmma::fragment<wmma::matrix_a, 16, 16, 16, __nv_bfloat16, wmma::row_major> ah[2], al[2];
            #pragma unroll
            for (int i = 0; i < 2; i++) {
                wmma::load_matrix_sync(ah[i], tile[0] + (wm*32 + i*16) * 40 + ks, 40);
                wmma::load_matrix_sync(al[i], tile[1] + (wm*32 + i*16) * 40 + ks, 40);
            }
            #pragma unroll
            for (int j = 0; j < 4; j++) {
                wmma::fragment<wmma::matrix_b, 16, 16, 16, __nv_bfloat16, wmma::col_major> bh, bl;
                wmma::load_matrix_sync(bh, tile[2] + (wn*64 + j*16) * 40 + ks, 40);
                wmma::load_matrix_sync(bl, tile[3] + (wn*64 + j*16) * 40 + ks, 40);
                #pragma unroll
                for (int i = 0; i < 2; i++) {
                    wmma::mma_sync(acc[i][j], ah[i], bh, acc[i][j]);
                    wmma::mma_sync(acc[i][j], ah[i], bl, acc[i][j]);
                    wmma::mma_sync(acc[i][j], al[i], bh, acc[i][j]);
                }
            }
        }
        __syncthreads();
    }

    float* stage = reinterpret_cast<float*>(smem) + w * 320;
    int r = lane >> 1, c0 = (lane & 1) * 8;
    #pragma unroll
    for (int i = 0; i < 2; i++) {
        #pragma unroll
        for (int j = 0; j < 4; j++) {
            wmma::store_matrix_sync(stage, acc[i][j], 20, wmma::mem_row_major);
            __syncwarp();
            int gm = m0 + wm*32 + i*16 + r;
            if (gm < M) {
                int nc = wn*64 + j*16 + c0;
                float4 v0, v1;
                v0.x = stage[r*20 + c0 + 0] + sbias[nc + 0];
                v0.y = stage[r*20 + c0 + 1] + sbias[nc + 1];
                v0.z = stage[r*20 + c0 + 2] + sbias[nc + 2];
                v0.w = stage[r*20 + c0 + 3] + sbias[nc + 3];
                v1.x = stage[r*20 + c0 + 4] + sbias[nc + 4];
                v1.y = stage[r*20 + c0 + 5] + sbias[nc + 5];
                v1.z = stage[r*20 + c0 + 6] + sbias[nc + 6];
                v1.w = stage[r*20 + c0 + 7] + sbias[nc + 7];
                if (relu) {
                    v0.x = fmaxf(v0.x, 0.f); v0.y = fmaxf(v0.y, 0.f);
                    v0.z = fmaxf(v0.z, 0.f); v0.w = fmaxf(v0.w, 0.f);
                    v1.x = fmaxf(v1.x, 0.f); v1.y = fmaxf(v1.y, 0.f);
                    v1.z = fmaxf(v1.z, 0.f); v1.w = fmaxf(v1.w, 0.f);
                }
                *reinterpret_cast<float4*>(&C[(size_t)gm * N + n0 + nc])     = v0;
                *reinterpret_cast<float4*>(&C[(size_t)gm * N + n0 + nc + 4]) = v1;
            }
            __syncwarp();
        }
    }
}

// ---------------- cluster LSTM v3: gate-major compute + hardware cluster barrier ----
// 16 clusters x 8 CTAs, 2 batches/cluster. Thread (j,kg): j=tid>>3, kg=tid&7.
// Computes all 4 gates for (gj = rk*32+j) for both batches; cell state in regs.
__global__ __cluster_dims__(8,1,1) __launch_bounds__(256, 1)
void lstm_kernel(const float* __restrict__ w_hh) {
    __shared__ __align__(16) float hbuf[2][2][288];   // [phase][batch][kg*36 + idx]

    int tid  = threadIdx.x;
    int rk   = blockIdx.x & 7;
    int cl   = blockIdx.x >> 3;
    int j    = tid >> 3;
    int kg   = tid & 7;
    int gj   = rk * 32 + j;

    // weights in registers: w2[gate][16] f32x2 over k-slice [kg*32, kg*32+32)
    ull w2[4][16];
    #pragma unroll
    for (int g = 0; g < 4; g++) {
        const ulonglong2* wp = reinterpret_cast<const ulonglong2*>(
            &w_hh[(size_t)(g*256 + gj) * 256 + kg*32]);
        #pragma unroll
        for (int i = 0; i < 8; i++) {
            ulonglong2 u = wp[i];
            w2[g][2*i]   = u.x;
            w2[g][2*i+1] = u.y;
        }
    }

    for (int i = tid; i < 2*2*288; i += 256) (&hbuf[0][0][0])[i] = 0.f;
    __syncthreads();
    cluster_sync_();    // zeroed hbuf visible cluster-wide

    uint32_t hb = smem_u32(&hbuf[0][0][0]);
    uint32_t rhb[8];
    #pragma unroll
    for (int rr = 0; rr < 8; rr++) rhb[rr] = mapa_(hb, (uint32_t)rr);

    const bool pw = (kg == 0);
    size_t gxb0 = ((size_t)(2*cl + 0) * SM1) * 1024 + gj;
    size_t gxb1 = ((size_t)(2*cl + 1) * SM1) * 1024 + gj;
    float gxc[8], gxn[8];
    if (pw) {
        #pragma unroll
        for (int g = 0; g < 4; g++) {
            gxc[g]     = __ldcg(&d_gx[gxb0 + g*256]);
            gxc[4 + g] = __ldcg(&d_gx[gxb1 + g*256]);
        }
    }
    float c0 = 0.f, c1 = 0.f;

    for (int t = 0; t < SM1; t++) {
        if (pw && t + 1 < SM1) {
            size_t o = (size_t)(t + 1) * 1024;
            #pragma unroll
            for (int g = 0; g < 4; g++) {
                gxn[g]     = __ldcg(&d_gx[gxb0 + o + g*256]);
                gxn[4 + g] = __ldcg(&d_gx[gxb1 + o + g*256]);
            }
        }
        int ph = t & 1;
        const ulonglong2* hp0 = reinterpret_cast<const ulonglong2*>(&hbuf[ph][0][kg*36]);
        const ulonglong2* hp1 = reinterpret_cast<const ulonglong2*>(&hbuf[ph][1][kg*36]);

        ull acc[4][2];
        #pragma unroll
        for (int g = 0; g < 4; g++) { acc[g][0] = 0ULL; acc[g][1] = 0ULL; }

        #pragma unroll
        for (int i = 0; i < 8; i++) {
            ulonglong2 u0 = hp0[i];
            ulonglong2 u1 = hp1[i];
            #pragma unroll
            for (int g = 0; g < 4; g++) {
                fma2(acc[g][0], w2[g][2*i],   u0.x);
                fma2(acc[g][0], w2[g][2*i+1], u0.y);
                fma2(acc[g][1], w2[g][2*i],   u1.x);
                fma2(acc[g][1], w2[g][2*i+1], u1.y);
            }
        }

        float s[8];
        #pragma unroll
        for (int g = 0; g < 4; g++) {
            float2 a0 = upk(acc[g][0]); s[g]     = a0.x + a0.y;
            float2 a1 = upk(acc[g][1]); s[4 + g] = a1.x + a1.y;
        }
        #pragma unroll
        for (int d = 4; d; d >>= 1) {
            #pragma unroll
            for (int v = 0; v < 8; v++)
                s[v] += __shfl_down_sync(0xffffffffu, s[v], d, 8);
        }

        if (pw) {
            float cn0 = fast_sig(s[1] + gxc[1]) * c0
                      + fast_sig(s[0] + gxc[0]) * fast_tanh(s[2] + gxc[2]);
            float h0  = fast_sig(s[3] + gxc[3]) * fast_tanh(cn0);
            float cn1 = fast_sig(s[5] + gxc[5]) * c1
                      + fast_sig(s[4] + gxc[4]) * fast_tanh(s[6] + gxc[6]);
            float h1  = fast_sig(s[7] + gxc[7]) * fast_tanh(cn1);
            c0 = cn0; c1 = cn1;

            size_t r0 = ((size_t)(2*cl + 0) * SM1 + t) * 256 + gj;
            size_t r1 = ((size_t)(2*cl + 1) * SM1 + t) * 256 + gj;
            d_hall[r0] = h0;
            d_hall[r1] = h1;
            __nv_bfloat16 hh0 = __float2bfloat16_rn(h0);
            __nv_bfloat16 hh1 = __float2bfloat16_rn(h1);
            g_hal_hi[r0] = hh0;
            g_hal_lo[r0] = __float2bfloat16_rn(h0 - __bfloat162float(hh0));
            g_hal_hi[r1] = hh1;
            g_hal_lo[r1] = __float2bfloat16_rn(h1 - __bfloat162float(hh1));

            uint32_t off0 = (uint32_t)((((t+1)&1)*2 + 0)*288 + rk*36 + j) * 4u;
            uint32_t off1 = off0 + 288u*4u;
            #pragma unroll
            for (int rr = 0; rr < 8; rr++) {
                st_dsmem(rhb[rr] + off0, h0);
                st_dsmem(rhb[rr] + off1, h1);
            }
            #pragma unroll
            for (int v = 0; v < 8; v++) gxc[v] = gxn[v];
        }
        // hardware cluster barrier: arrive has release semantics for the
        // shared::cluster stores above; wait gives acquire for next-phase reads.
        cluster_sync_();
    }
}

// ---------------- gathered output heads ----------------
__device__ __forceinline__ float warp_sum(float v) {
    #pragma unroll
    for (int o = 16; o; o >>= 1) v += __shfl_xor_sync(0xffffffffu, v, o);
    return v;
}

__global__ __launch_bounds__(256) void gather_kernel(
    const int* __restrict__ qshft, const int* __restrict__ cshft,
    const float* __restrict__ qn_ow, const float* __restrict__ qn_ob,
    const float* __restrict__ cn_ow, const float* __restrict__ cn_ob,
    const float* __restrict__ qa_ow, const float* __restrict__ qa_ob,
    const float* __restrict__ ca_ow, const float* __restrict__ ca_ob,
    float* __restrict__ out)
{
    int m = blockIdx.x * 8 + (threadIdx.x >> 5);
    int lane = threadIdx.x & 31;

    float acc = 0.f;
    for (int k = lane; k < 768; k += 32)
        acc += d_hq[(size_t)m*768 + k] * qn_ow[k];
    float yqn = sigmoidf_(warp_sum(acc) + qn_ob[0]);

    float ysum = 0.f; int cnt = 0;
    #pragma unroll
    for (int j = 0; j < MC; j++) {
        int cc = cshft[m*MC + j];
        if (cc >= 0) {
            float a = 0.f;
            for (int k = lane; k < 768; k += 32)
                a += d_hc[(size_t)m*768 + k] * cn_ow[(size_t)cc*768 + k];
            ysum += sigmoidf_(warp_sum(a) + cn_ob[cc]);
            cnt++;
        }
    }
    float ycn = ysum / (float)max(cnt, 1);

    int qi = qshft[m];
    float a2 = 0.f;
    for (int k = lane; k < 256; k += 32)
        a2 += d_hqa[(size_t)m*256 + k] * qa_ow[(size_t)qi*256 + k];
    float yqa = sigmoidf_(warp_sum(a2) + qa_ob[qi]);

    float ysum2 = 0.f; int cnt2 = 0;
    #pragma unroll
    for (int j = 0; j < MC; j++) {
        int cc = cshft[m*MC + j];
        if (cc >= 0) {
            float a = 0.f;
            for (int k = lane; k < 256; k += 32)
                a += d_hca[(size_t)m*256 + k] * ca_ow[(size_t)cc*256 + k];
            ysum2 += sigmoidf_(warp_sum(a) + ca_ob[cc]);
            cnt2++;
        }
    }
    float yca = ysum2 / (float)max(cnt2, 1);

    if (lane == 0) {
        out[m]            = yqn;
        out[MTOT + m]     = ycn;
        out[2*MTOT + m]   = yqa;
        out[3*MTOT + m]   = yca;
    }
}

// ---------------- launch ----------------
extern "C" void kernel_launch(void* const* d_in, const int* in_sizes, int n_in,
                              void* d_out, int out_size) {
    const int*   q           = (const int*)d_in[0];
    const int*   c           = (const int*)d_in[1];
    const int*   r           = (const int*)d_in[2];
    const int*   qshft       = (const int*)d_in[3];
    const int*   cshft       = (const int*)d_in[4];
    const float* que_emb     = (const float*)d_in[5];
    const float* concept_emb = (const float*)d_in[6];
    const float* w_ih        = (const float*)d_in[7];
    const float* w_hh        = (const float*)d_in[8];
    const float* b_ih        = (const float*)d_in[9];
    const float* b_hh        = (const float*)d_in[10];
    const float* qn_lw = (const float*)d_in[11];
    const float* qn_lb = (const float*)d_in[12];
    const float* qn_ow = (const float*)d_in[13];
    const float* qn_ob = (const float*)d_in[14];
    const float* cn_lw = (const float*)d_in[15];
    const float* cn_lb = (const float*)d_in[16];
    const float* cn_ow = (const float*)d_in[17];
    const float* cn_ob = (const float*)d_in[18];
    const float* qa_lw = (const float*)d_in[19];
    const float* qa_lb = (const float*)d_in[20];
    const float* qa_ow = (const float*)d_in[21];
    const float* qa_ob = (const float*)d_in[22];
    const float* ca_lw = (const float*)d_in[23];
    const float* ca_lb = (const float*)d_in[24];
    const float* ca_ow = (const float*)d_in[25];
    const float* ca_ob = (const float*)d_in[26];
    float* out = (float*)d_out;

    float* p_gx;  cudaGetSymbolAddress((void**)&p_gx,  d_gx);
    float* p_hq;  cudaGetSymbolAddress((void**)&p_hq,  d_hq);
    float* p_hc;  cudaGetSymbolAddress((void**)&p_hc,  d_hc);
    float* p_hqa; cudaGetSymbolAddress((void**)&p_hqa, d_hqa);
    float* p_hca; cudaGetSymbolAddress((void**)&p_hca, d_hca);
    __nv_bfloat16 *p_qca_hi, *p_qca_lo, *p_wih_hi, *p_wih_lo;
    __nv_bfloat16 *p_hnx_hi, *p_hnx_lo, *p_hal_hi, *p_hal_lo;
    __nv_bfloat16 *p_wqn_hi, *p_wqn_lo, *p_wcn_hi, *p_wcn_lo;
    __nv_bfloat16 *p_wqa_hi, *p_wqa_lo, *p_wca_hi, *p_wca_lo;
    cudaGetSymbolAddress((void**)&p_qca_hi, g_qca_hi);
    cudaGetSymbolAddress((void**)&p_qca_lo, g_qca_lo);
    cudaGetSymbolAddress((void**)&p_wih_hi, g_wih_hi);
    cudaGetSymbolAddress((void**)&p_wih_lo, g_wih_lo);
    cudaGetSymbolAddress((void**)&p_hnx_hi, g_hnx_hi);
    cudaGetSymbolAddress((void**)&p_hnx_lo, g_hnx_lo);
    cudaGetSymbolAddress((void**)&p_hal_hi, g_hal_hi);
    cudaGetSymbolAddress((void**)&p_hal_lo, g_hal_lo);
    cudaGetSymbolAddress((void**)&p_wqn_hi, g_wqn_hi);
    cudaGetSymbolAddress((void**)&p_wqn_lo, g_wqn_lo);
    cudaGetSymbolAddress((void**)&p_wcn_hi, g_wcn_hi);
    cudaGetSymbolAddress((void**)&p_wcn_lo, g_wcn_lo);
    cudaGetSymbolAddress((void**)&p_wqa_hi, g_wqa_hi);
    cudaGetSymbolAddress((void**)&p_wqa_lo, g_wqa_lo);
    cudaGetSymbolAddress((void**)&p_wca_hi, g_wca_hi);
    cudaGetSymbolAddress((void**)&p_wca_lo, g_wca_lo);

    // (1) embeddings
    embed_kernel<<<BB*SS, 256>>>(q, c, r, que_emb, concept_emb);
    // (2) w_ih split
    cvt_split<<<(1024*1024/4 + 255)/256, 256>>>(w_ih, p_wih_hi, p_wih_lo, 1024*1024);
    // (3) gx = qca @ w_ih^T + b_ih + b_hh
    { dim3 g(8, 50); mma_gemm<<<g, 256, GEMM_SMEM>>>(p_qca_hi, p_qca_lo, p_wih_hi, p_wih_lo,
                                                     b_ih, b_hh, p_gx, MTOT, 1024, 1024, 0); }
    // (4) LSTM  <-- profiled launch slot
    lstm_kernel<<<128, 256>>>(w_hh);
    // (5) hnext assembly
    hnext_kernel<<<MTOT, 256>>>();
    // (6-9) weight splits
    cvt_split<<<(768*768/4 + 255)/256, 256>>>(qn_lw, p_wqn_hi, p_wqn_lo, 768*768);
    cvt_split<<<(768*768/4 + 255)/256, 256>>>(cn_lw, p_wcn_hi, p_wcn_lo, 768*768);
    cvt_split<<<(256*256/4 + 255)/256, 256>>>(qa_lw, p_wqa_hi, p_wqa_lo, 256*256);
    cvt_split<<<(256*256/4 + 255)/256, 256>>>(ca_lw, p_wca_hi, p_wca_lo, 256*256);
    // (10-13) hidden GEMMs
    { dim3 g(6, 50); mma_gemm<<<g, 256, GEMM_SMEM>>>(p_hnx_hi, p_hnx_lo, p_wqn_hi, p_wqn_lo,
                                                     qn_lb, nullptr, p_hq, MTOT, 768, 768, 1); }
    { dim3 g(6, 50); mma_gemm<<<g, 256, GEMM_SMEM>>>(p_hnx_hi, p_hnx_lo, p_wcn_hi, p_wcn_lo,
                                                     cn_lb, nullptr, p_hc, MTOT, 768, 768, 1); }
    { dim3 g(2, 50); mma_gemm<<<g, 256, GEMM_SMEM>>>(p_hal_hi, p_hal_lo, p_wqa_hi, p_wqa_lo,
                                                     qa_lb, nullptr, p_hqa, MTOT, 256, 256, 1); }
    { dim3 g(2, 50); mma_gemm<<<g, 256, GEMM_SMEM>>>(p_hal_hi, p_hal_lo, p_wca_hi, p_wca_lo,
                                                     ca_lb, nullptr, p_hca, MTOT, 256, 256, 1); }
    // (14) gathered heads
    gather_kernel<<<MTOT/8, 256>>>(qshft, cshft, qn_ow, qn_ob, cn_ow, cn_ob,
                                   qa_ow, qa_ob, ca_ow, ca_ob, out);
    (void)in_sizes; (void)n_in; (void)out_size;
}